// round 7
// baseline (speedup 1.0000x reference)
#include <cuda_runtime.h>
#include <math.h>
#include <math_constants.h>

#define T_LEN   8192
#define N_SC    16
#define TTILE   512
#define NTH     256
#define HALO    258
#define SXN     1048                      // x tile + halo + slack (mult of 8)
#define SXO     523                       // odd-aligned pair array (float2 count)
#define SW      520                       // smem row stride for [18][SW] planes
#define MAXW    3408                      // >= sum of padded wavelet lengths (3368)
#define WPAD    8                         // prefetch overrun pad for g_wq
#define C1COLS  514                       // conv1 output cols (c = 1..514)

// ---------------- wavelet tables (filled by init kernel each launch) ----------------
__device__ float2 g_wtab[MAXW];           // (wr, wi) per padded tap (halo path)
__device__ float4 g_wq[MAXW + WPAD];      // (wr, wr, wi, wi) per padded tap (main path)
__device__ int    g_Lp[N_SC];             // padded length (multiple of 4)
__device__ int    g_off[N_SC];            // padded offset (multiple of 4)
__device__ int    g_p[N_SC];              // half width L/2
__device__ int    g_sh[N_SC];             // leading zero taps

// LPT-balanced schedule: warp-pair grp handles these 4 scales (chunk = warp parity)
__constant__ int c_sched[4][4] = { {13,10,5,1}, {14,9,6,4}, {15,8,7,3}, {12,11,2,0} };

__global__ void wav_init_kernel()
{
    const double la = log10(2.0);
    const double lb = log10(200.0);
    int Ls[N_SC], Ps[N_SC], Sh[N_SC], Lp[N_SC], off[N_SC];
    int tot = 0;
    for (int i = 0; i < N_SC; ++i) {
        double e = (i == N_SC - 1) ? lb : la + (lb - la) * ((double)i / (double)(N_SC - 1));
        double s = pow(10.0, e);
        int L = (int)(6.0 * s);           // trunc, matches Python int()
        if (L > 512) L = 512;
        if ((L & 1) == 0) ++L;
        int p = L >> 1;
        int sh = ((2 - p) % 4 + 4) % 4;   // keeps st a multiple of 4 (cols start at cc=2)
        int lp = (L + sh + 3) & ~3;
        Ls[i] = L; Ps[i] = p; Sh[i] = sh; Lp[i] = lp; off[i] = tot; tot += lp;
    }
    if (threadIdx.x < N_SC) {
        g_Lp[threadIdx.x]  = Lp[threadIdx.x];
        g_off[threadIdx.x] = off[threadIdx.x];
        g_p[threadIdx.x]   = Ps[threadIdx.x];
        g_sh[threadIdx.x]  = Sh[threadIdx.x];
    }

    for (int idx = threadIdx.x; idx < MAXW + WPAD; idx += blockDim.x) {
        float2 v = make_float2(0.f, 0.f);
        if (idx < tot) {
            int s = 0;
            while (s < N_SC - 1 && idx >= off[s + 1]) ++s;
            int k = idx - off[s] - Sh[s];     // unpadded tap index
            int L = Ls[s];
            if (k >= 0 && k < L) {
                double e  = (s == N_SC - 1) ? lb : la + (lb - la) * ((double)s / (double)(N_SC - 1));
                double sc = pow(10.0, e);
                double lo = -(double)((L + 1) / 2);
                double hi =  (double)(L / 2);
                double t  = (k == L - 1) ? hi : lo + (double)k * ((double)L / (double)(L - 1));
                double ts = t / sc;
                double nrm = 1.0 / (pow(CUDART_PI, 0.25) * sqrt(sc));
                double g = nrm * exp(-0.5 * ts * ts);
                v = make_float2((float)(g * cos(5.0 * ts)), (float)(g * sin(5.0 * ts)));
            }
        }
        if (idx < MAXW) g_wtab[idx] = v;
        g_wq[idx] = make_float4(v.x, v.x, v.y, v.y);
    }
}

// ---------------- packed f32x2 helpers ----------------
__device__ __forceinline__ void unpack2(unsigned long long a, float& lo, float& hi)
{
    unsigned ul, uh;
    asm("mov.b64 {%0, %1}, %2;" : "=r"(ul), "=r"(uh) : "l"(a));
    lo = __uint_as_float(ul); hi = __uint_as_float(uh);
}
#define FMA2(acc, w, xx) asm("fma.rn.f32x2 %0, %1, %2, %0;" : "+l"(acc) : "l"(w), "l"(xx))

// ---------------- fused CWT + correction-net + inverse kernel ----------------
__global__ __launch_bounds__(NTH, 2)
void wav_main_kernel(const float* __restrict__ x,
                     const float* __restrict__ w1,
                     const float* __restrict__ b1,
                     const float* __restrict__ w2,
                     const float* __restrict__ b2,
                     const float* __restrict__ blendl,
                     const float* __restrict__ lsc,
                     float* __restrict__ out)
{
    extern __shared__ float sm[];
    float*  sx  = sm;                       // SXN scalars (even pairs = float2 view)
    float2* sxo = (float2*)(sm + SXN);      // SXO odd-aligned pairs (x[2i+1], x[2i+2])
    float*  scw = sm + SXN + 2 * SXO;       // [18][SW] CWT magnitudes, rows 0/17 zero
    float*  sh1 = scw + 18 * SW;            // [18][SW] conv1+gelu, rows 0/17 zero
    float*  w1e = sh1 + 18 * SW;            // 144 folded conv1 weights
    float*  w2s = w1e + 144;                // 12 (9 used)
    int*    sLp = (int*)(w2s + 12);         // 16
    int*    sOf = sLp + 16;                 // 16
    int*    sP  = sOf + 16;                 // 16
    int*    sSh = sP + 16;                  // 16

    const int tid  = threadIdx.x;
    const int wid  = tid >> 5;
    const int lane = tid & 31;
    const int row  = blockIdx.y;            // b*C + c
    const int ch   = row & 31;
    const int t0   = blockIdx.x * TTILE;
    const float* xr = x + (size_t)row * T_LEN;

    // ---- phase A1: x tile with reflect halo ----
    for (int i = tid; i < SXN; i += NTH) {
        int g = t0 - HALO + i;
        if (g < 0) g = -g;                          // reflect
        if (g >= T_LEN) g = 2 * (T_LEN - 1) - g;
        sx[i] = xr[g];
    }
    for (int i = tid; i < SW; i += NTH) {
        scw[i] = 0.f; scw[17 * SW + i] = 0.f;
        sh1[i] = 0.f; sh1[17 * SW + i] = 0.f;
    }
    if (tid < N_SC) {
        sLp[tid] = g_Lp[tid]; sOf[tid] = g_off[tid];
        sP[tid]  = g_p[tid];  sSh[tid] = g_sh[tid];
    }
    if (tid < 144) {
        int s = tid / 9, r = tid - s * 9, ds = r / 3;
        int si = s + ds - 1; si = si < 0 ? 0 : (si > 15 ? 15 : si);
        w1e[tid] = w1[ch * 9 + r] * expf(lsc[si]);
    }
    if (tid < 9) w2s[tid] = w2[ch * 9 + tid];
    __syncthreads();

    // ---- phase A2: odd-aligned pair array ----
    for (int i = tid; i < SXO; i += NTH)
        sxo[i] = make_float2(sx[2 * i + 1], sx[2 * i + 2]);
    __syncthreads();

    // ---- phase B1: main CWT, cols 2..513, 8 cols/lane as 4 col-pairs, f32x2 ----
    const int grp = wid >> 1;                       // warp-pair id 0..3
    const int chk = wid & 1;                        // 256-col chunk 0/1
    #pragma unroll 1
    for (int it = 0; it < 4; ++it) {
        int s  = c_sched[grp][it];
        int Lp = sLp[s];
        int nb = Lp >> 2;
        int c0 = 2 + (chk << 8) + (lane << 3);      // 8 consecutive cols per lane
        int st = c0 + 256 - sP[s] - sSh[s];         // multiple of 4 by construction
        const ulonglong2* ep = (const ulonglong2*)(sx + st);        // even pairs
        const ulonglong2* op = (const ulonglong2*)sxo + (st >> 2);  // odd pairs
        const ulonglong2* wq = (const ulonglong2*)g_wq + sOf[s];    // (wr,wr | wi,wi)

        ulonglong2 E01 = ep[0], E23 = ep[1], E45 = ep[2];
        ulonglong2 O01 = op[0], O23 = op[1], O45 = op[2];
        unsigned long long e0 = E01.x, e1 = E01.y, e2 = E23.x,
                           e3 = E23.y, e4 = E45.x, e5 = E45.y;
        unsigned long long o0 = O01.x, o1 = O01.y, o2 = O23.x,
                           o3 = O23.y, o4 = O45.x, o5 = O45.y;
        ulonglong2 wA = wq[0], wB = wq[1], wC = wq[2], wD = wq[3];
        unsigned long long r0 = 0ull, r1 = 0ull, r2 = 0ull, r3 = 0ull;
        unsigned long long i0 = 0ull, i1 = 0ull, i2 = 0ull, i3 = 0ull;

        #pragma unroll 3
        for (int b = 0; b < nb; ++b) {
            ulonglong2 nA = wq[4], nB = wq[5], nC = wq[6], nD = wq[7];  // prefetch
            wq += 4;
            ulonglong2 En = ep[b + 3];
            ulonglong2 On = op[b + 3];
            // tap 4b   (weights dup'd in wA.x/.y): even pairs
            FMA2(r0, wA.x, e0); FMA2(r1, wA.x, e1); FMA2(r2, wA.x, e2); FMA2(r3, wA.x, e3);
            FMA2(i0, wA.y, e0); FMA2(i1, wA.y, e1); FMA2(i2, wA.y, e2); FMA2(i3, wA.y, e3);
            // tap 4b+1: odd pairs
            FMA2(r0, wB.x, o0); FMA2(r1, wB.x, o1); FMA2(r2, wB.x, o2); FMA2(r3, wB.x, o3);
            FMA2(i0, wB.y, o0); FMA2(i1, wB.y, o1); FMA2(i2, wB.y, o2); FMA2(i3, wB.y, o3);
            // tap 4b+2: even pairs shifted by 1
            FMA2(r0, wC.x, e1); FMA2(r1, wC.x, e2); FMA2(r2, wC.x, e3); FMA2(r3, wC.x, e4);
            FMA2(i0, wC.y, e1); FMA2(i1, wC.y, e2); FMA2(i2, wC.y, e3); FMA2(i3, wC.y, e4);
            // tap 4b+3: odd pairs shifted by 1
            FMA2(r0, wD.x, o1); FMA2(r1, wD.x, o2); FMA2(r2, wD.x, o3); FMA2(r3, wD.x, o4);
            FMA2(i0, wD.y, o1); FMA2(i1, wD.y, o2); FMA2(i2, wD.y, o3); FMA2(i3, wD.y, o4);
            // shift windows by 2 pairs (renamed by unroll 3)
            e0 = e2; e1 = e3; e2 = e4; e3 = e5; e4 = En.x; e5 = En.y;
            o0 = o2; o1 = o3; o2 = o4; o3 = o5; o4 = On.x; o5 = On.y;
            wA = nA; wB = nB; wC = nC; wD = nD;
        }
        float* dst = scw + (s + 1) * SW + c0;
        float rl, rh, il, ih;
        unpack2(r0, rl, rh); unpack2(i0, il, ih);
        dst[0] = sqrtf(fmaf(rl, rl, il * il)); dst[1] = sqrtf(fmaf(rh, rh, ih * ih));
        unpack2(r1, rl, rh); unpack2(i1, il, ih);
        dst[2] = sqrtf(fmaf(rl, rl, il * il)); dst[3] = sqrtf(fmaf(rh, rh, ih * ih));
        unpack2(r2, rl, rh); unpack2(i2, il, ih);
        dst[4] = sqrtf(fmaf(rl, rl, il * il)); dst[5] = sqrtf(fmaf(rh, rh, ih * ih));
        unpack2(r3, rl, rh); unpack2(i3, il, ih);
        dst[6] = sqrtf(fmaf(rl, rl, il * il)); dst[7] = sqrtf(fmaf(rh, rh, ih * ih));
    }

    // ---- phase B2: halo cols {0,1,514,515}, tap-split + shuffle reduce ----
    {
        #pragma unroll 1
        for (int it = 0; it < 8; ++it) {
            int task = wid + (it << 3);             // 0..63
            int s = task >> 2, h = task & 3;
            int cc = (h == 0) ? 0 : (h == 1) ? 1 : (h == 2) ? 514 : 515;
            int Lp = sLp[s];
            int stc = cc + 256 - sP[s] - sSh[s];
            const float2* wp = g_wtab + sOf[s];
            float re = 0.f, im = 0.f;
            for (int k = lane; k < Lp; k += 32) {
                int ix = stc + k; ix = ix < 0 ? 0 : ix;   // clamped: weight is 0 there
                float xv = sx[ix];
                float2 w = __ldg(wp + k);
                re = fmaf(w.x, xv, re); im = fmaf(w.y, xv, im);
            }
            #pragma unroll
            for (int o = 16; o; o >>= 1) {
                re += __shfl_down_sync(0xffffffffu, re, o);
                im += __shfl_down_sync(0xffffffffu, im, o);
            }
            if (lane == 0) {
                int t = t0 - 2 + cc;
                scw[(s + 1) * SW + cc] =
                    ((unsigned)t < T_LEN) ? sqrtf(fmaf(re, re, im * im)) : 0.f;
            }
        }
    }
    __syncthreads();

    // ---- phase C: conv1 (scale-corr folded into weights) + exact GELU ----
    const float b1v = b1[ch];
    for (int item = tid; item < N_SC * C1COLS; item += NTH) {
        int s = item / C1COLS;
        int c = item - s * C1COLS + 1;              // 1..514
        int t = t0 - 2 + c;
        const float* r0 = scw + s * SW + (c - 1);
        const float* r1 = r0 + SW;
        const float* r2 = r1 + SW;
        const float* wv = w1e + s * 9;
        float v = b1v;
        v = fmaf(wv[0], r0[0], v); v = fmaf(wv[1], r0[1], v); v = fmaf(wv[2], r0[2], v);
        v = fmaf(wv[3], r1[0], v); v = fmaf(wv[4], r1[1], v); v = fmaf(wv[5], r1[2], v);
        v = fmaf(wv[6], r2[0], v); v = fmaf(wv[7], r2[1], v); v = fmaf(wv[8], r2[2], v);
        float g = 0.5f * v * (1.f + erff(v * 0.70710678118654752440f));
        // conv2's SAME zero-pad: h1 at t=-1 / t=8192 must be exactly 0
        sh1[(s + 1) * SW + c] = ((unsigned)t < T_LEN) ? g : 0.f;
    }
    __syncthreads();

    // ---- phase D: conv2 + GELU + blend + ratio-mean over scales + write ----
    const float blend = 1.f / (1.f + expf(-blendl[0]));
    const float b2v = b2[ch];
    float wl[9];
    #pragma unroll
    for (int i = 0; i < 9; ++i) wl[i] = w2s[i];
    for (int c = 2 + tid; c < TTILE + 2; c += NTH) {
        float acc = 0.f;
        #pragma unroll 4
        for (int s = 1; s <= N_SC; ++s) {
            const float* r0 = sh1 + (s - 1) * SW + (c - 1);
            const float* r1 = r0 + SW;
            const float* r2 = r1 + SW;
            float v = b2v;
            v = fmaf(wl[0], r0[0], v); v = fmaf(wl[1], r0[1], v); v = fmaf(wl[2], r0[2], v);
            v = fmaf(wl[3], r1[0], v); v = fmaf(wl[4], r1[1], v); v = fmaf(wl[5], r1[2], v);
            v = fmaf(wl[6], r2[0], v); v = fmaf(wl[7], r2[1], v); v = fmaf(wl[8], r2[2], v);
            float h  = 0.5f * v * (1.f + erff(v * 0.70710678118654752440f));
            float cw = scw[s * SW + c];
            float bl = blend * h + (1.f - blend) * cw;
            acc += __fdividef(bl, cw + 1e-8f);
        }
        out[(size_t)row * T_LEN + (t0 + c - 2)] = sx[c + 256] * acc * (1.f / 16.f);
    }
}

extern "C" void kernel_launch(void* const* d_in, const int* in_sizes, int n_in,
                              void* d_out, int out_size)
{
    const float* x  = (const float*)d_in[0];
    const float* w1 = (const float*)d_in[1];
    const float* b1 = (const float*)d_in[2];
    const float* w2 = (const float*)d_in[3];
    const float* b2 = (const float*)d_in[4];
    const float* bl = (const float*)d_in[5];
    const float* ls = (const float*)d_in[6];
    float* out = (float*)d_out;

    const int rows = in_sizes[0] / T_LEN;   // B*C = 256

    const size_t smem = (size_t)(SXN + 2 * SXO + 2 * 18 * SW + 144 + 12) * sizeof(float)
                        + 4 * 16 * sizeof(int);
    cudaFuncSetAttribute(wav_main_kernel, cudaFuncAttributeMaxDynamicSharedMemorySize, (int)smem);

    wav_init_kernel<<<1, 256>>>();
    dim3 grid(T_LEN / TTILE, rows);
    wav_main_kernel<<<grid, NTH, smem>>>(x, w1, b1, w2, b2, bl, ls, out);
}

// round 8
// speedup vs baseline: 1.3653x; 1.3653x over previous
#include <cuda_runtime.h>
#include <math.h>
#include <math_constants.h>

#define T_LEN   8192
#define N_SC    16
#define TTILE   512
#define NTH     256
#define HALO    258
#define SXN     1040                      // x tile + halo + slack (16B-mult count)
#define SW      520                       // smem row stride for [18][SW] planes
#define MAXW    3408                      // >= sum of padded wavelet lengths (3368)
#define C1COLS  514                       // conv1 output cols (c = 1..514)

// ---------------- wavelet tables (filled by init kernel each launch) ----------------
__device__ float2 g_wtab[MAXW];           // padded: sh leading zeros, tail zeros to %4
__device__ int    g_Lp[N_SC];             // padded length (multiple of 4)
__device__ int    g_off[N_SC];            // padded offset (multiple of 4)
__device__ int    g_p[N_SC];              // half width L/2
__device__ int    g_sh[N_SC];             // leading zero taps
__device__ int    g_tot;

// LPT-balanced schedule: warp-pair grp handles these 4 scales (chunk = warp parity)
__constant__ int c_sched[4][4] = { {13,10,5,1}, {14,9,6,4}, {15,8,7,3}, {12,11,2,0} };

__global__ void wav_init_kernel()
{
    const double la = log10(2.0);
    const double lb = log10(200.0);
    int Ls[N_SC], Ps[N_SC], Sh[N_SC], Lp[N_SC], off[N_SC];
    int tot = 0;
    for (int i = 0; i < N_SC; ++i) {
        double e = (i == N_SC - 1) ? lb : la + (lb - la) * ((double)i / (double)(N_SC - 1));
        double s = pow(10.0, e);
        int L = (int)(6.0 * s);           // trunc, matches Python int()
        if (L > 512) L = 512;
        if ((L & 1) == 0) ++L;
        int p = L >> 1;
        int sh = ((2 - p) % 4 + 4) % 4;   // aligns x window start (cols start at cc=2)
        int lp = (L + sh + 3) & ~3;
        Ls[i] = L; Ps[i] = p; Sh[i] = sh; Lp[i] = lp; off[i] = tot; tot += lp;
    }
    if (threadIdx.x < N_SC) {
        g_Lp[threadIdx.x]  = Lp[threadIdx.x];
        g_off[threadIdx.x] = off[threadIdx.x];
        g_p[threadIdx.x]   = Ps[threadIdx.x];
        g_sh[threadIdx.x]  = Sh[threadIdx.x];
    }
    if (threadIdx.x == 0) g_tot = tot;

    for (int idx = threadIdx.x; idx < tot; idx += blockDim.x) {
        int s = 0;
        while (s < N_SC - 1 && idx >= off[s + 1]) ++s;
        int k = idx - off[s] - Sh[s];     // unpadded tap index
        int L = Ls[s];
        float2 v = make_float2(0.f, 0.f);
        if (k >= 0 && k < L) {
            double e  = (s == N_SC - 1) ? lb : la + (lb - la) * ((double)s / (double)(N_SC - 1));
            double sc = pow(10.0, e);
            double lo = -(double)((L + 1) / 2);
            double hi =  (double)(L / 2);
            double t  = (k == L - 1) ? hi : lo + (double)k * ((double)L / (double)(L - 1));
            double ts = t / sc;
            double nrm = 1.0 / (pow(CUDART_PI, 0.25) * sqrt(sc));
            double g = nrm * exp(-0.5 * ts * ts);
            v = make_float2((float)(g * cos(5.0 * ts)), (float)(g * sin(5.0 * ts)));
        }
        g_wtab[idx] = v;
    }
}

// ---------------- packed f32x2 helpers ----------------
__device__ __forceinline__ unsigned long long packdup(float v)
{
    unsigned long long r;
    unsigned u = __float_as_uint(v);
    asm("mov.b64 %0, {%1, %1};" : "=l"(r) : "r"(u));
    return r;
}
__device__ __forceinline__ void unpack2(unsigned long long a, float& lo, float& hi)
{
    unsigned ul, uh;
    asm("mov.b64 {%0, %1}, %2;" : "=r"(ul), "=r"(uh) : "l"(a));
    lo = __uint_as_float(ul); hi = __uint_as_float(uh);
}
#define FMA2(acc, w, xx) asm("fma.rn.f32x2 %0, %1, %2, %0;" : "+l"(acc) : "l"(w), "l"(xx))

// ---------------- fused CWT + correction-net + inverse kernel ----------------
__global__ __launch_bounds__(NTH, 2)
void wav_main_kernel(const float* __restrict__ x,
                     const float* __restrict__ w1,
                     const float* __restrict__ b1,
                     const float* __restrict__ w2,
                     const float* __restrict__ b2,
                     const float* __restrict__ blendl,
                     const float* __restrict__ lsc,
                     float* __restrict__ out)
{
    extern __shared__ float sm[];
    float*  sx  = sm;                       // SXN: x tile + reflect halo (16B aligned)
    float2* swt = (float2*)(sm + SXN);      // MAXW float2 padded wavelets
    float*  scw = sm + SXN + 2 * MAXW;      // [18][SW] CWT magnitudes, rows 0/17 zero
    float*  sh1 = scw + 18 * SW;            // [18][SW] conv1+gelu, rows 0/17 zero
    float*  w1e = sh1 + 18 * SW;            // 144 folded conv1 weights
    float*  w2s = w1e + 144;                // 12 (9 used)
    int*    sLp = (int*)(w2s + 12);         // 16
    int*    sOf = sLp + 16;                 // 16
    int*    sP  = sOf + 16;                 // 16
    int*    sSh = sP + 16;                  // 16

    const int tid  = threadIdx.x;
    const int wid  = tid >> 5;
    const int lane = tid & 31;
    const int row  = blockIdx.y;            // b*C + c
    const int ch   = row & 31;
    const int t0   = blockIdx.x * TTILE;
    const float* xr = x + (size_t)row * T_LEN;

    // ---- phase A: loads ----
    for (int i = tid; i < SXN; i += NTH) {
        int g = t0 - HALO + i;
        if (g < 0) g = -g;                          // reflect
        if (g >= T_LEN) g = 2 * (T_LEN - 1) - g;
        sx[i] = xr[g];
    }
    const int tot = g_tot;
    for (int i = tid; i < tot; i += NTH) swt[i] = g_wtab[i];
    for (int i = tid; i < SW; i += NTH) {
        scw[i] = 0.f; scw[17 * SW + i] = 0.f;
        sh1[i] = 0.f; sh1[17 * SW + i] = 0.f;
    }
    if (tid < N_SC) {
        sLp[tid] = g_Lp[tid]; sOf[tid] = g_off[tid];
        sP[tid]  = g_p[tid];  sSh[tid] = g_sh[tid];
    }
    if (tid < 144) {
        int s = tid / 9, r = tid - s * 9, ds = r / 3;
        int si = s + ds - 1; si = si < 0 ? 0 : (si > 15 ? 15 : si);
        w1e[tid] = w1[ch * 9 + r] * expf(lsc[si]);
    }
    if (tid < 9) w2s[tid] = w2[ch * 9 + tid];
    __syncthreads();

    // ---- phase B1: main CWT, cols 2..513, 8 cols/lane, LPT units, packed f32x2 ----
    const int grp = wid >> 1;                       // warp-pair id 0..3
    const int chk = wid & 1;                        // 256-col chunk 0/1
    #pragma unroll 1
    for (int it = 0; it < 4; ++it) {
        int s = c_sched[grp][it];
        int Lp = sLp[s];
        const ulonglong2* wp = (const ulonglong2*)swt + (sOf[s] >> 1);
        int c0 = 2 + (chk << 8) + (lane << 3);      // 8 consecutive cols per lane
        int st = c0 + 256 - sP[s] - sSh[s];         // multiple of 4 by construction
        const float4* xv4 = (const float4*)(sx + st);
        float4 xa = xv4[0];
        float4 xb = xv4[1];
        unsigned long long q0 = packdup(xa.x), q1 = packdup(xa.y),
                           q2 = packdup(xa.z), q3 = packdup(xa.w);
        unsigned long long q4 = packdup(xb.x), q5 = packdup(xb.y),
                           q6 = packdup(xb.z), q7 = packdup(xb.w);
        unsigned long long a0 = 0ull, a1 = 0ull, a2 = 0ull, a3 = 0ull,
                           a4 = 0ull, a5 = 0ull, a6 = 0ull, a7 = 0ull;
        int nb = Lp >> 2;
        // weight double-buffer: block b's weights are loaded during block b-1
        ulonglong2 wA = wp[0], wB = wp[1];
        wp += 2;
        #pragma unroll 4
        for (int b = 0; b < nb; ++b) {
            float4 xn = xv4[b + 2];                 // x prefetch, distance 2
            ulonglong2 nA = wp[0], nB = wp[1];      // weight prefetch, distance 1
            wp += 2;
            unsigned long long q8  = packdup(xn.x), q9  = packdup(xn.y),
                               q10 = packdup(xn.z), q11 = packdup(xn.w);
            // tap 0: cols j use q[j]
            FMA2(a0, wA.x, q0); FMA2(a1, wA.x, q1); FMA2(a2, wA.x, q2); FMA2(a3, wA.x, q3);
            FMA2(a4, wA.x, q4); FMA2(a5, wA.x, q5); FMA2(a6, wA.x, q6); FMA2(a7, wA.x, q7);
            // tap 1
            FMA2(a0, wA.y, q1); FMA2(a1, wA.y, q2); FMA2(a2, wA.y, q3); FMA2(a3, wA.y, q4);
            FMA2(a4, wA.y, q5); FMA2(a5, wA.y, q6); FMA2(a6, wA.y, q7); FMA2(a7, wA.y, q8);
            // tap 2
            FMA2(a0, wB.x, q2); FMA2(a1, wB.x, q3); FMA2(a2, wB.x, q4); FMA2(a3, wB.x, q5);
            FMA2(a4, wB.x, q6); FMA2(a5, wB.x, q7); FMA2(a6, wB.x, q8); FMA2(a7, wB.x, q9);
            // tap 3
            FMA2(a0, wB.y, q3); FMA2(a1, wB.y, q4); FMA2(a2, wB.y, q5); FMA2(a3, wB.y, q6);
            FMA2(a4, wB.y, q7); FMA2(a5, wB.y, q8); FMA2(a6, wB.y, q9); FMA2(a7, wB.y, q10);
            // shift window by 4 (period-2 rename; unroll 4 keeps it mov-free)
            q0 = q4; q1 = q5; q2 = q6; q3 = q7;
            q4 = q8; q5 = q9; q6 = q10; q7 = q11;
            wA = nA; wB = nB;
        }
        float* dst = scw + (s + 1) * SW + c0;
        float cr, ci;
        unpack2(a0, cr, ci); dst[0] = sqrtf(fmaf(cr, cr, ci * ci));
        unpack2(a1, cr, ci); dst[1] = sqrtf(fmaf(cr, cr, ci * ci));
        unpack2(a2, cr, ci); dst[2] = sqrtf(fmaf(cr, cr, ci * ci));
        unpack2(a3, cr, ci); dst[3] = sqrtf(fmaf(cr, cr, ci * ci));
        unpack2(a4, cr, ci); dst[4] = sqrtf(fmaf(cr, cr, ci * ci));
        unpack2(a5, cr, ci); dst[5] = sqrtf(fmaf(cr, cr, ci * ci));
        unpack2(a6, cr, ci); dst[6] = sqrtf(fmaf(cr, cr, ci * ci));
        unpack2(a7, cr, ci); dst[7] = sqrtf(fmaf(cr, cr, ci * ci));
    }

    // ---- phase B2: halo cols {0,1,514,515}, tap-split + shuffle reduce ----
    {
        #pragma unroll 1
        for (int it = 0; it < 8; ++it) {
            int task = wid + (it << 3);             // 0..63
            int s = task >> 2, h = task & 3;
            int cc = (h == 0) ? 0 : (h == 1) ? 1 : (h == 2) ? 514 : 515;
            int Lp = sLp[s];
            int stc = cc + 256 - sP[s] - sSh[s];
            const float2* wp = swt + sOf[s];
            float re = 0.f, im = 0.f;
            for (int k = lane; k < Lp; k += 32) {
                int ix = stc + k; ix = ix < 0 ? 0 : ix;   // clamped: weight is 0 there
                float xv = sx[ix];
                float2 w = wp[k];
                re = fmaf(w.x, xv, re); im = fmaf(w.y, xv, im);
            }
            #pragma unroll
            for (int o = 16; o; o >>= 1) {
                re += __shfl_down_sync(0xffffffffu, re, o);
                im += __shfl_down_sync(0xffffffffu, im, o);
            }
            if (lane == 0) {
                int t = t0 - 2 + cc;
                scw[(s + 1) * SW + cc] =
                    ((unsigned)t < T_LEN) ? sqrtf(fmaf(re, re, im * im)) : 0.f;
            }
        }
    }
    __syncthreads();

    // ---- phase C: conv1 (scale-corr folded into weights) + exact GELU ----
    const float b1v = b1[ch];
    for (int item = tid; item < N_SC * C1COLS; item += NTH) {
        int s = item / C1COLS;
        int c = item - s * C1COLS + 1;              // 1..514
        int t = t0 - 2 + c;
        const float* r0 = scw + s * SW + (c - 1);
        const float* r1 = r0 + SW;
        const float* r2 = r1 + SW;
        const float* wv = w1e + s * 9;
        float v = b1v;
        v = fmaf(wv[0], r0[0], v); v = fmaf(wv[1], r0[1], v); v = fmaf(wv[2], r0[2], v);
        v = fmaf(wv[3], r1[0], v); v = fmaf(wv[4], r1[1], v); v = fmaf(wv[5], r1[2], v);
        v = fmaf(wv[6], r2[0], v); v = fmaf(wv[7], r2[1], v); v = fmaf(wv[8], r2[2], v);
        float g = 0.5f * v * (1.f + erff(v * 0.70710678118654752440f));
        // conv2's SAME zero-pad: h1 at t=-1 / t=8192 must be exactly 0
        sh1[(s + 1) * SW + c] = ((unsigned)t < T_LEN) ? g : 0.f;
    }
    __syncthreads();

    // ---- phase D: conv2 + GELU + blend + ratio-mean over scales + write ----
    const float blend = 1.f / (1.f + expf(-blendl[0]));
    const float b2v = b2[ch];
    float wl[9];
    #pragma unroll
    for (int i = 0; i < 9; ++i) wl[i] = w2s[i];
    for (int c = 2 + tid; c < TTILE + 2; c += NTH) {
        float acc = 0.f;
        #pragma unroll 4
        for (int s = 1; s <= N_SC; ++s) {
            const float* r0 = sh1 + (s - 1) * SW + (c - 1);
            const float* r1 = r0 + SW;
            const float* r2 = r1 + SW;
            float v = b2v;
            v = fmaf(wl[0], r0[0], v); v = fmaf(wl[1], r0[1], v); v = fmaf(wl[2], r0[2], v);
            v = fmaf(wl[3], r1[0], v); v = fmaf(wl[4], r1[1], v); v = fmaf(wl[5], r1[2], v);
            v = fmaf(wl[6], r2[0], v); v = fmaf(wl[7], r2[1], v); v = fmaf(wl[8], r2[2], v);
            float h  = 0.5f * v * (1.f + erff(v * 0.70710678118654752440f));
            float cw = scw[s * SW + c];
            float bl = blend * h + (1.f - blend) * cw;
            acc += __fdividef(bl, cw + 1e-8f);
        }
        out[(size_t)row * T_LEN + (t0 + c - 2)] = sx[c + 256] * acc * (1.f / 16.f);
    }
}

extern "C" void kernel_launch(void* const* d_in, const int* in_sizes, int n_in,
                              void* d_out, int out_size)
{
    const float* x  = (const float*)d_in[0];
    const float* w1 = (const float*)d_in[1];
    const float* b1 = (const float*)d_in[2];
    const float* w2 = (const float*)d_in[3];
    const float* b2 = (const float*)d_in[4];
    const float* bl = (const float*)d_in[5];
    const float* ls = (const float*)d_in[6];
    float* out = (float*)d_out;

    const int rows = in_sizes[0] / T_LEN;   // B*C = 256

    const size_t smem = (size_t)(SXN + 2 * MAXW + 2 * 18 * SW + 144 + 12) * sizeof(float)
                        + 4 * 16 * sizeof(int);
    cudaFuncSetAttribute(wav_main_kernel, cudaFuncAttributeMaxDynamicSharedMemorySize, (int)smem);

    wav_init_kernel<<<1, 256>>>();
    dim3 grid(T_LEN / TTILE, rows);
    wav_main_kernel<<<grid, NTH, smem>>>(x, w1, b1, w2, b2, bl, ls, out);
}

// round 9
// speedup vs baseline: 1.6922x; 1.2395x over previous
#include <cuda_runtime.h>
#include <math.h>
#include <math_constants.h>

#define T_LEN   8192
#define N_SC    16
#define TTILE   512
#define NTH     256
#define HALO    258
#define SXN     1040                      // x tile + halo + slack (16B-mult count)
#define SW      520                       // smem row stride for [18][SW] planes
#define MAXW    3408                      // >= sum of padded wavelet lengths (3368)
#define C1COLS  514                       // conv1 output cols (c = 1..514)

// ---------------- wavelet tables (filled by init kernel each launch) ----------------
__device__ float2 g_wtab[MAXW];           // padded: sh leading zeros, tail zeros to %4
__device__ int    g_Lp[N_SC];             // padded length (multiple of 4)
__device__ int    g_off[N_SC];            // padded offset (multiple of 4)
__device__ int    g_p[N_SC];              // half width L/2
__device__ int    g_sh[N_SC];             // leading zero taps
__device__ int    g_tot;

// LPT-balanced schedule: warp-pair grp handles these 4 scales (chunk = warp parity)
__constant__ int c_sched[4][4] = { {13,10,5,1}, {14,9,6,4}, {15,8,7,3}, {12,11,2,0} };

// Parallel init: one block per scale, 256 threads per block. Same fp64 math as
// before (bit-identical tables), but the DP work now spreads across 16 SMs
// instead of serializing ~3400 pow/exp/cos/sin chains on one SM.
__global__ void wav_init_kernel()
{
    const double la = log10(2.0);
    const double lb = log10(200.0);
    int Ls[N_SC], Ps[N_SC], Sh[N_SC], Lp[N_SC], off[N_SC];
    int tot = 0;
    #pragma unroll
    for (int i = 0; i < N_SC; ++i) {
        double e = (i == N_SC - 1) ? lb : la + (lb - la) * ((double)i / (double)(N_SC - 1));
        double s = pow(10.0, e);
        int L = (int)(6.0 * s);           // trunc, matches Python int()
        if (L > 512) L = 512;
        if ((L & 1) == 0) ++L;
        int p = L >> 1;
        int sh = ((2 - p) % 4 + 4) % 4;   // aligns x window start (cols start at cc=2)
        int lp = (L + sh + 3) & ~3;
        Ls[i] = L; Ps[i] = p; Sh[i] = sh; Lp[i] = lp; off[i] = tot; tot += lp;
    }
    const int s = blockIdx.x;             // this block's scale
    if (s == 0) {
        if (threadIdx.x < N_SC) {
            g_Lp[threadIdx.x]  = Lp[threadIdx.x];
            g_off[threadIdx.x] = off[threadIdx.x];
            g_p[threadIdx.x]   = Ps[threadIdx.x];
            g_sh[threadIdx.x]  = Sh[threadIdx.x];
        }
        if (threadIdx.x == 0) g_tot = tot;
    }

    const double e  = (s == N_SC - 1) ? lb : la + (lb - la) * ((double)s / (double)(N_SC - 1));
    const double sc = pow(10.0, e);
    const int L = Ls[s];
    const double lo = -(double)((L + 1) / 2);
    const double hi =  (double)(L / 2);
    const double nrm = 1.0 / (pow(CUDART_PI, 0.25) * sqrt(sc));
    for (int k = threadIdx.x; k < Lp[s]; k += blockDim.x) {
        int ku = k - Sh[s];               // unpadded tap index
        float2 v = make_float2(0.f, 0.f);
        if (ku >= 0 && ku < L) {
            double t  = (ku == L - 1) ? hi : lo + (double)ku * ((double)L / (double)(L - 1));
            double ts = t / sc;
            double g = nrm * exp(-0.5 * ts * ts);
            v = make_float2((float)(g * cos(5.0 * ts)), (float)(g * sin(5.0 * ts)));
        }
        g_wtab[off[s] + k] = v;
    }
}

// ---------------- packed f32x2 helpers ----------------
__device__ __forceinline__ unsigned long long packdup(float v)
{
    unsigned long long r;
    unsigned u = __float_as_uint(v);
    asm("mov.b64 %0, {%1, %1};" : "=l"(r) : "r"(u));
    return r;
}
__device__ __forceinline__ void unpack2(unsigned long long a, float& lo, float& hi)
{
    unsigned ul, uh;
    asm("mov.b64 {%0, %1}, %2;" : "=r"(ul), "=r"(uh) : "l"(a));
    lo = __uint_as_float(ul); hi = __uint_as_float(uh);
}
#define FMA2(acc, w, xx) asm("fma.rn.f32x2 %0, %1, %2, %0;" : "+l"(acc) : "l"(w), "l"(xx))

// ---------------- fused CWT + correction-net + inverse kernel ----------------
__global__ __launch_bounds__(NTH, 2)
void wav_main_kernel(const float* __restrict__ x,
                     const float* __restrict__ w1,
                     const float* __restrict__ b1,
                     const float* __restrict__ w2,
                     const float* __restrict__ b2,
                     const float* __restrict__ blendl,
                     const float* __restrict__ lsc,
                     float* __restrict__ out)
{
    extern __shared__ float sm[];
    float*  sx  = sm;                       // SXN: x tile + reflect halo (16B aligned)
    float2* swt = (float2*)(sm + SXN);      // MAXW float2 padded wavelets
    float*  scw = sm + SXN + 2 * MAXW;      // [18][SW] CWT magnitudes, rows 0/17 zero
    float*  sh1 = scw + 18 * SW;            // [18][SW] conv1+gelu, rows 0/17 zero
    float*  w1e = sh1 + 18 * SW;            // 144 folded conv1 weights
    float*  w2s = w1e + 144;                // 12 (9 used)
    int*    sLp = (int*)(w2s + 12);         // 16
    int*    sOf = sLp + 16;                 // 16
    int*    sP  = sOf + 16;                 // 16
    int*    sSh = sP + 16;                  // 16

    const int tid  = threadIdx.x;
    const int wid  = tid >> 5;
    const int lane = tid & 31;
    const int row  = blockIdx.y;            // b*C + c
    const int ch   = row & 31;
    const int t0   = blockIdx.x * TTILE;
    const float* xr = x + (size_t)row * T_LEN;

    // ---- phase A: loads ----
    for (int i = tid; i < SXN; i += NTH) {
        int g = t0 - HALO + i;
        if (g < 0) g = -g;                          // reflect
        if (g >= T_LEN) g = 2 * (T_LEN - 1) - g;
        sx[i] = xr[g];
    }
    const int tot = g_tot;
    for (int i = tid; i < tot; i += NTH) swt[i] = g_wtab[i];
    for (int i = tid; i < SW; i += NTH) {
        scw[i] = 0.f; scw[17 * SW + i] = 0.f;
        sh1[i] = 0.f; sh1[17 * SW + i] = 0.f;
    }
    if (tid < N_SC) {
        sLp[tid] = g_Lp[tid]; sOf[tid] = g_off[tid];
        sP[tid]  = g_p[tid];  sSh[tid] = g_sh[tid];
    }
    if (tid < 144) {
        int s = tid / 9, r = tid - s * 9, ds = r / 3;
        int si = s + ds - 1; si = si < 0 ? 0 : (si > 15 ? 15 : si);
        w1e[tid] = w1[ch * 9 + r] * expf(lsc[si]);
    }
    if (tid < 9) w2s[tid] = w2[ch * 9 + tid];
    __syncthreads();

    // ---- phase B1: main CWT, cols 2..513, 8 cols/lane, LPT units, packed f32x2 ----
    const int grp = wid >> 1;                       // warp-pair id 0..3
    const int chk = wid & 1;                        // 256-col chunk 0/1
    #pragma unroll 1
    for (int it = 0; it < 4; ++it) {
        int s = c_sched[grp][it];
        int Lp = sLp[s];
        const ulonglong2* wp = (const ulonglong2*)swt + (sOf[s] >> 1);
        int c0 = 2 + (chk << 8) + (lane << 3);      // 8 consecutive cols per lane
        int st = c0 + 256 - sP[s] - sSh[s];         // multiple of 4 by construction
        const float4* xv4 = (const float4*)(sx + st);
        float4 xa = xv4[0];
        float4 xb = xv4[1];
        unsigned long long q0 = packdup(xa.x), q1 = packdup(xa.y),
                           q2 = packdup(xa.z), q3 = packdup(xa.w);
        unsigned long long q4 = packdup(xb.x), q5 = packdup(xb.y),
                           q6 = packdup(xb.z), q7 = packdup(xb.w);
        unsigned long long a0 = 0ull, a1 = 0ull, a2 = 0ull, a3 = 0ull,
                           a4 = 0ull, a5 = 0ull, a6 = 0ull, a7 = 0ull;
        int nb = Lp >> 2;
        // weight double-buffer: block b's weights are loaded during block b-1
        ulonglong2 wA = wp[0], wB = wp[1];
        wp += 2;
        #pragma unroll 4
        for (int b = 0; b < nb; ++b) {
            float4 xn = xv4[b + 2];                 // x prefetch, distance 2
            ulonglong2 nA = wp[0], nB = wp[1];      // weight prefetch, distance 1
            wp += 2;
            unsigned long long q8  = packdup(xn.x), q9  = packdup(xn.y),
                               q10 = packdup(xn.z), q11 = packdup(xn.w);
            // tap 0: cols j use q[j]
            FMA2(a0, wA.x, q0); FMA2(a1, wA.x, q1); FMA2(a2, wA.x, q2); FMA2(a3, wA.x, q3);
            FMA2(a4, wA.x, q4); FMA2(a5, wA.x, q5); FMA2(a6, wA.x, q6); FMA2(a7, wA.x, q7);
            // tap 1
            FMA2(a0, wA.y, q1); FMA2(a1, wA.y, q2); FMA2(a2, wA.y, q3); FMA2(a3, wA.y, q4);
            FMA2(a4, wA.y, q5); FMA2(a5, wA.y, q6); FMA2(a6, wA.y, q7); FMA2(a7, wA.y, q8);
            // tap 2
            FMA2(a0, wB.x, q2); FMA2(a1, wB.x, q3); FMA2(a2, wB.x, q4); FMA2(a3, wB.x, q5);
            FMA2(a4, wB.x, q6); FMA2(a5, wB.x, q7); FMA2(a6, wB.x, q8); FMA2(a7, wB.x, q9);
            // tap 3
            FMA2(a0, wB.y, q3); FMA2(a1, wB.y, q4); FMA2(a2, wB.y, q5); FMA2(a3, wB.y, q6);
            FMA2(a4, wB.y, q7); FMA2(a5, wB.y, q8); FMA2(a6, wB.y, q9); FMA2(a7, wB.y, q10);
            // shift window by 4 (period-2 rename; unroll 4 keeps it mov-free)
            q0 = q4; q1 = q5; q2 = q6; q3 = q7;
            q4 = q8; q5 = q9; q6 = q10; q7 = q11;
            wA = nA; wB = nB;
        }
        float* dst = scw + (s + 1) * SW + c0;
        float cr, ci;
        unpack2(a0, cr, ci); dst[0] = sqrtf(fmaf(cr, cr, ci * ci));
        unpack2(a1, cr, ci); dst[1] = sqrtf(fmaf(cr, cr, ci * ci));
        unpack2(a2, cr, ci); dst[2] = sqrtf(fmaf(cr, cr, ci * ci));
        unpack2(a3, cr, ci); dst[3] = sqrtf(fmaf(cr, cr, ci * ci));
        unpack2(a4, cr, ci); dst[4] = sqrtf(fmaf(cr, cr, ci * ci));
        unpack2(a5, cr, ci); dst[5] = sqrtf(fmaf(cr, cr, ci * ci));
        unpack2(a6, cr, ci); dst[6] = sqrtf(fmaf(cr, cr, ci * ci));
        unpack2(a7, cr, ci); dst[7] = sqrtf(fmaf(cr, cr, ci * ci));
    }

    // ---- phase B2: halo cols {0,1,514,515}, tap-split + shuffle reduce ----
    {
        #pragma unroll 1
        for (int it = 0; it < 8; ++it) {
            int task = wid + (it << 3);             // 0..63
            int s = task >> 2, h = task & 3;
            int cc = (h == 0) ? 0 : (h == 1) ? 1 : (h == 2) ? 514 : 515;
            int Lp = sLp[s];
            int stc = cc + 256 - sP[s] - sSh[s];
            const float2* wp = swt + sOf[s];
            float re = 0.f, im = 0.f;
            for (int k = lane; k < Lp; k += 32) {
                int ix = stc + k; ix = ix < 0 ? 0 : ix;   // clamped: weight is 0 there
                float xv = sx[ix];
                float2 w = wp[k];
                re = fmaf(w.x, xv, re); im = fmaf(w.y, xv, im);
            }
            #pragma unroll
            for (int o = 16; o; o >>= 1) {
                re += __shfl_down_sync(0xffffffffu, re, o);
                im += __shfl_down_sync(0xffffffffu, im, o);
            }
            if (lane == 0) {
                int t = t0 - 2 + cc;
                scw[(s + 1) * SW + cc] =
                    ((unsigned)t < T_LEN) ? sqrtf(fmaf(re, re, im * im)) : 0.f;
            }
        }
    }
    __syncthreads();

    // ---- phase C: conv1 (scale-corr folded into weights) + exact GELU ----
    const float b1v = b1[ch];
    for (int item = tid; item < N_SC * C1COLS; item += NTH) {
        int s = item / C1COLS;
        int c = item - s * C1COLS + 1;              // 1..514
        int t = t0 - 2 + c;
        const float* r0 = scw + s * SW + (c - 1);
        const float* r1 = r0 + SW;
        const float* r2 = r1 + SW;
        const float* wv = w1e + s * 9;
        float v = b1v;
        v = fmaf(wv[0], r0[0], v); v = fmaf(wv[1], r0[1], v); v = fmaf(wv[2], r0[2], v);
        v = fmaf(wv[3], r1[0], v); v = fmaf(wv[4], r1[1], v); v = fmaf(wv[5], r1[2], v);
        v = fmaf(wv[6], r2[0], v); v = fmaf(wv[7], r2[1], v); v = fmaf(wv[8], r2[2], v);
        float g = 0.5f * v * (1.f + erff(v * 0.70710678118654752440f));
        // conv2's SAME zero-pad: h1 at t=-1 / t=8192 must be exactly 0
        sh1[(s + 1) * SW + c] = ((unsigned)t < T_LEN) ? g : 0.f;
    }
    __syncthreads();

    // ---- phase D: conv2 + GELU + blend + ratio-mean over scales + write ----
    const float blend = 1.f / (1.f + expf(-blendl[0]));
    const float b2v = b2[ch];
    float wl[9];
    #pragma unroll
    for (int i = 0; i < 9; ++i) wl[i] = w2s[i];
    for (int c = 2 + tid; c < TTILE + 2; c += NTH) {
        float acc = 0.f;
        #pragma unroll 4
        for (int s = 1; s <= N_SC; ++s) {
            const float* r0 = sh1 + (s - 1) * SW + (c - 1);
            const float* r1 = r0 + SW;
            const float* r2 = r1 + SW;
            float v = b2v;
            v = fmaf(wl[0], r0[0], v); v = fmaf(wl[1], r0[1], v); v = fmaf(wl[2], r0[2], v);
            v = fmaf(wl[3], r1[0], v); v = fmaf(wl[4], r1[1], v); v = fmaf(wl[5], r1[2], v);
            v = fmaf(wl[6], r2[0], v); v = fmaf(wl[7], r2[1], v); v = fmaf(wl[8], r2[2], v);
            float h  = 0.5f * v * (1.f + erff(v * 0.70710678118654752440f));
            float cw = scw[s * SW + c];
            float bl = blend * h + (1.f - blend) * cw;
            acc += __fdividef(bl, cw + 1e-8f);
        }
        out[(size_t)row * T_LEN + (t0 + c - 2)] = sx[c + 256] * acc * (1.f / 16.f);
    }
}

extern "C" void kernel_launch(void* const* d_in, const int* in_sizes, int n_in,
                              void* d_out, int out_size)
{
    const float* x  = (const float*)d_in[0];
    const float* w1 = (const float*)d_in[1];
    const float* b1 = (const float*)d_in[2];
    const float* w2 = (const float*)d_in[3];
    const float* b2 = (const float*)d_in[4];
    const float* bl = (const float*)d_in[5];
    const float* ls = (const float*)d_in[6];
    float* out = (float*)d_out;

    const int rows = in_sizes[0] / T_LEN;   // B*C = 256

    const size_t smem = (size_t)(SXN + 2 * MAXW + 2 * 18 * SW + 144 + 12) * sizeof(float)
                        + 4 * 16 * sizeof(int);
    cudaFuncSetAttribute(wav_main_kernel, cudaFuncAttributeMaxDynamicSharedMemorySize, (int)smem);

    wav_init_kernel<<<N_SC, 256>>>();      // parallel: one block per scale
    dim3 grid(T_LEN / TTILE, rows);
    wav_main_kernel<<<grid, NTH, smem>>>(x, w1, b1, w2, b2, bl, ls, out);
}

// round 10
// speedup vs baseline: 2.1032x; 1.2429x over previous
#include <cuda_runtime.h>
#include <math.h>
#include <math_constants.h>

#define T_LEN   8192
#define N_SC    16
#define TTILE   512
#define NTH     256
#define HALO    258
#define SXN     1040                      // x tile + halo + slack (16B-mult count)
#define SW      520                       // smem row stride for [18][SW] planes
#define MAXW    3408                      // >= sum of padded wavelet lengths (3368)
#define C1COLS  514                       // conv1 output cols (c = 1..514)

// ---------------- wavelet tables (filled by init kernel each launch) ----------------
__device__ float2 g_wtab[MAXW];           // padded: sh leading zeros, tail zeros to %4
__device__ int    g_Lp[N_SC];             // padded length (multiple of 4)
__device__ int    g_off[N_SC];            // padded offset (multiple of 4)
__device__ int    g_p[N_SC];              // half width L/2
__device__ int    g_sh[N_SC];             // leading zero taps
__device__ int    g_tot;

// LPT-balanced schedule: warp-pair grp handles these 4 scales (chunk = warp parity)
__constant__ int c_sched[4][4] = { {13,10,5,1}, {14,9,6,4}, {15,8,7,3}, {12,11,2,0} };

// Parallel init v3: grid (5 chunks, 16 scales) x 128 threads.
// fp64 pow for the scale values is computed ONCE per scale (threads 0-15 into
// shared), not per-thread; offsets derived with integer math. Each thread then
// fills at most one tap (~3 fp64 transcendentals). Bit-identical tables.
__global__ void wav_init_kernel()
{
    __shared__ double sh_sc[N_SC];
    __shared__ int    sh_L[N_SC];

    const double la = log10(2.0);
    const double lb = log10(200.0);
    const int tid = threadIdx.x;

    if (tid < N_SC) {
        double e = (tid == N_SC - 1) ? lb
                 : la + (lb - la) * ((double)tid / (double)(N_SC - 1));
        double sv = pow(10.0, e);
        int L = (int)(6.0 * sv);          // trunc, matches Python int()
        if (L > 512) L = 512;
        if ((L & 1) == 0) ++L;
        sh_sc[tid] = sv;
        sh_L[tid]  = L;
    }
    __syncthreads();

    // integer-only metadata derivation (cheap, per-thread)
    const int s = blockIdx.y;             // this block's scale
    int off = 0, Lcur = 0, Pcur = 0, Shc = 0, Lpc = 0, tot = 0;
    #pragma unroll
    for (int i = 0; i < N_SC; ++i) {
        int L  = sh_L[i];
        int p  = L >> 1;
        int sh = ((2 - p) % 4 + 4) % 4;
        int lp = (L + sh + 3) & ~3;
        if (i < s) off += lp;
        if (i == s) { Lcur = L; Pcur = p; Shc = sh; Lpc = lp; }
        tot += lp;
    }

    if (blockIdx.x == 0 && blockIdx.y == 0) {
        if (tid < N_SC) {
            int o2 = 0;
            int L = sh_L[tid], p = L >> 1;
            int sh = ((2 - p) % 4 + 4) % 4;
            int lp = (L + sh + 3) & ~3;
            for (int i = 0; i < tid; ++i) {
                int Li = sh_L[i], pi = Li >> 1;
                int shi = ((2 - pi) % 4 + 4) % 4;
                o2 += (Li + shi + 3) & ~3;
            }
            g_Lp[tid] = lp; g_off[tid] = o2; g_p[tid] = p; g_sh[tid] = sh;
        }
        if (tid == 0) g_tot = tot;
    }

    // tap fill: one tap per thread
    const int k = blockIdx.x * 128 + tid;
    if (k >= Lpc) return;
    const double sc = sh_sc[s];
    const int L = Lcur;
    float2 v = make_float2(0.f, 0.f);
    int ku = k - Shc;                     // unpadded tap index
    if (ku >= 0 && ku < L) {
        double lo = -(double)((L + 1) / 2);
        double hi =  (double)(L / 2);
        double t  = (ku == L - 1) ? hi : lo + (double)ku * ((double)L / (double)(L - 1));
        double ts = t / sc;
        double nrm = 1.0 / (pow(CUDART_PI, 0.25) * sqrt(sc));
        double g = nrm * exp(-0.5 * ts * ts);
        v = make_float2((float)(g * cos(5.0 * ts)), (float)(g * sin(5.0 * ts)));
    }
    g_wtab[off + k] = v;
}

// ---------------- packed f32x2 helpers ----------------
__device__ __forceinline__ unsigned long long packdup(float v)
{
    unsigned long long r;
    unsigned u = __float_as_uint(v);
    asm("mov.b64 %0, {%1, %1};" : "=l"(r) : "r"(u));
    return r;
}
__device__ __forceinline__ void unpack2(unsigned long long a, float& lo, float& hi)
{
    unsigned ul, uh;
    asm("mov.b64 {%0, %1}, %2;" : "=r"(ul), "=r"(uh) : "l"(a));
    lo = __uint_as_float(ul); hi = __uint_as_float(uh);
}
#define FMA2(acc, w, xx) asm("fma.rn.f32x2 %0, %1, %2, %0;" : "+l"(acc) : "l"(w), "l"(xx))

// ---------------- fused CWT + correction-net + inverse kernel ----------------
__global__ __launch_bounds__(NTH, 2)
void wav_main_kernel(const float* __restrict__ x,
                     const float* __restrict__ w1,
                     const float* __restrict__ b1,
                     const float* __restrict__ w2,
                     const float* __restrict__ b2,
                     const float* __restrict__ blendl,
                     const float* __restrict__ lsc,
                     float* __restrict__ out)
{
    extern __shared__ float sm[];
    float*  sx  = sm;                       // SXN: x tile + reflect halo (16B aligned)
    float2* swt = (float2*)(sm + SXN);      // MAXW float2 padded wavelets
    float*  scw = sm + SXN + 2 * MAXW;      // [18][SW] CWT magnitudes, rows 0/17 zero
    float*  sh1 = scw + 18 * SW;            // [18][SW] conv1+gelu, rows 0/17 zero
    float*  w1e = sh1 + 18 * SW;            // 144 folded conv1 weights
    float*  w2s = w1e + 144;                // 12 (9 used)
    int*    sLp = (int*)(w2s + 12);         // 16
    int*    sOf = sLp + 16;                 // 16
    int*    sP  = sOf + 16;                 // 16
    int*    sSh = sP + 16;                  // 16

    const int tid  = threadIdx.x;
    const int wid  = tid >> 5;
    const int lane = tid & 31;
    const int row  = blockIdx.y;            // b*C + c
    const int ch   = row & 31;
    const int t0   = blockIdx.x * TTILE;
    const float* xr = x + (size_t)row * T_LEN;

    // ---- phase A: loads ----
    for (int i = tid; i < SXN; i += NTH) {
        int g = t0 - HALO + i;
        if (g < 0) g = -g;                          // reflect
        if (g >= T_LEN) g = 2 * (T_LEN - 1) - g;
        sx[i] = xr[g];
    }
    const int tot = g_tot;
    for (int i = tid; i < tot; i += NTH) swt[i] = g_wtab[i];
    for (int i = tid; i < SW; i += NTH) {
        scw[i] = 0.f; scw[17 * SW + i] = 0.f;
        sh1[i] = 0.f; sh1[17 * SW + i] = 0.f;
    }
    if (tid < N_SC) {
        sLp[tid] = g_Lp[tid]; sOf[tid] = g_off[tid];
        sP[tid]  = g_p[tid];  sSh[tid] = g_sh[tid];
    }
    if (tid < 144) {
        int s = tid / 9, r = tid - s * 9, ds = r / 3;
        int si = s + ds - 1; si = si < 0 ? 0 : (si > 15 ? 15 : si);
        w1e[tid] = w1[ch * 9 + r] * expf(lsc[si]);
    }
    if (tid < 9) w2s[tid] = w2[ch * 9 + tid];
    __syncthreads();

    // ---- phase B1: main CWT, cols 2..513, 8 cols/lane, LPT units, packed f32x2 ----
    const int grp = wid >> 1;                       // warp-pair id 0..3
    const int chk = wid & 1;                        // 256-col chunk 0/1
    #pragma unroll 1
    for (int it = 0; it < 4; ++it) {
        int s = c_sched[grp][it];
        int Lp = sLp[s];
        const ulonglong2* wp = (const ulonglong2*)swt + (sOf[s] >> 1);
        int c0 = 2 + (chk << 8) + (lane << 3);      // 8 consecutive cols per lane
        int st = c0 + 256 - sP[s] - sSh[s];         // multiple of 4 by construction
        const float4* xv4 = (const float4*)(sx + st);
        float4 xa = xv4[0];
        float4 xb = xv4[1];
        unsigned long long q0 = packdup(xa.x), q1 = packdup(xa.y),
                           q2 = packdup(xa.z), q3 = packdup(xa.w);
        unsigned long long q4 = packdup(xb.x), q5 = packdup(xb.y),
                           q6 = packdup(xb.z), q7 = packdup(xb.w);
        unsigned long long a0 = 0ull, a1 = 0ull, a2 = 0ull, a3 = 0ull,
                           a4 = 0ull, a5 = 0ull, a6 = 0ull, a7 = 0ull;
        int nb = Lp >> 2;
        // weight double-buffer: block b's weights are loaded during block b-1
        ulonglong2 wA = wp[0], wB = wp[1];
        wp += 2;
        #pragma unroll 4
        for (int b = 0; b < nb; ++b) {
            float4 xn = xv4[b + 2];                 // x prefetch, distance 2
            ulonglong2 nA = wp[0], nB = wp[1];      // weight prefetch, distance 1
            wp += 2;
            unsigned long long q8  = packdup(xn.x), q9  = packdup(xn.y),
                               q10 = packdup(xn.z), q11 = packdup(xn.w);
            // tap 0: cols j use q[j]
            FMA2(a0, wA.x, q0); FMA2(a1, wA.x, q1); FMA2(a2, wA.x, q2); FMA2(a3, wA.x, q3);
            FMA2(a4, wA.x, q4); FMA2(a5, wA.x, q5); FMA2(a6, wA.x, q6); FMA2(a7, wA.x, q7);
            // tap 1
            FMA2(a0, wA.y, q1); FMA2(a1, wA.y, q2); FMA2(a2, wA.y, q3); FMA2(a3, wA.y, q4);
            FMA2(a4, wA.y, q5); FMA2(a5, wA.y, q6); FMA2(a6, wA.y, q7); FMA2(a7, wA.y, q8);
            // tap 2
            FMA2(a0, wB.x, q2); FMA2(a1, wB.x, q3); FMA2(a2, wB.x, q4); FMA2(a3, wB.x, q5);
            FMA2(a4, wB.x, q6); FMA2(a5, wB.x, q7); FMA2(a6, wB.x, q8); FMA2(a7, wB.x, q9);
            // tap 3
            FMA2(a0, wB.y, q3); FMA2(a1, wB.y, q4); FMA2(a2, wB.y, q5); FMA2(a3, wB.y, q6);
            FMA2(a4, wB.y, q7); FMA2(a5, wB.y, q8); FMA2(a6, wB.y, q9); FMA2(a7, wB.y, q10);
            // shift window by 4 (period-2 rename; unroll 4 keeps it mov-free)
            q0 = q4; q1 = q5; q2 = q6; q3 = q7;
            q4 = q8; q5 = q9; q6 = q10; q7 = q11;
            wA = nA; wB = nB;
        }
        float* dst = scw + (s + 1) * SW + c0;
        float cr, ci;
        unpack2(a0, cr, ci); dst[0] = sqrtf(fmaf(cr, cr, ci * ci));
        unpack2(a1, cr, ci); dst[1] = sqrtf(fmaf(cr, cr, ci * ci));
        unpack2(a2, cr, ci); dst[2] = sqrtf(fmaf(cr, cr, ci * ci));
        unpack2(a3, cr, ci); dst[3] = sqrtf(fmaf(cr, cr, ci * ci));
        unpack2(a4, cr, ci); dst[4] = sqrtf(fmaf(cr, cr, ci * ci));
        unpack2(a5, cr, ci); dst[5] = sqrtf(fmaf(cr, cr, ci * ci));
        unpack2(a6, cr, ci); dst[6] = sqrtf(fmaf(cr, cr, ci * ci));
        unpack2(a7, cr, ci); dst[7] = sqrtf(fmaf(cr, cr, ci * ci));
    }

    // ---- phase B2: halo cols {0,1,514,515}, tap-split + shuffle reduce ----
    {
        #pragma unroll 1
        for (int it = 0; it < 8; ++it) {
            int task = wid + (it << 3);             // 0..63
            int s = task >> 2, h = task & 3;
            int cc = (h == 0) ? 0 : (h == 1) ? 1 : (h == 2) ? 514 : 515;
            int Lp = sLp[s];
            int stc = cc + 256 - sP[s] - sSh[s];
            const float2* wp = swt + sOf[s];
            float re = 0.f, im = 0.f;
            for (int k = lane; k < Lp; k += 32) {
                int ix = stc + k; ix = ix < 0 ? 0 : ix;   // clamped: weight is 0 there
                float xv = sx[ix];
                float2 w = wp[k];
                re = fmaf(w.x, xv, re); im = fmaf(w.y, xv, im);
            }
            #pragma unroll
            for (int o = 16; o; o >>= 1) {
                re += __shfl_down_sync(0xffffffffu, re, o);
                im += __shfl_down_sync(0xffffffffu, im, o);
            }
            if (lane == 0) {
                int t = t0 - 2 + cc;
                scw[(s + 1) * SW + cc] =
                    ((unsigned)t < T_LEN) ? sqrtf(fmaf(re, re, im * im)) : 0.f;
            }
        }
    }
    __syncthreads();

    // ---- phase C: conv1 (scale-corr folded into weights) + exact GELU ----
    const float b1v = b1[ch];
    for (int item = tid; item < N_SC * C1COLS; item += NTH) {
        int s = item / C1COLS;
        int c = item - s * C1COLS + 1;              // 1..514
        int t = t0 - 2 + c;
        const float* r0 = scw + s * SW + (c - 1);
        const float* r1 = r0 + SW;
        const float* r2 = r1 + SW;
        const float* wv = w1e + s * 9;
        float v = b1v;
        v = fmaf(wv[0], r0[0], v); v = fmaf(wv[1], r0[1], v); v = fmaf(wv[2], r0[2], v);
        v = fmaf(wv[3], r1[0], v); v = fmaf(wv[4], r1[1], v); v = fmaf(wv[5], r1[2], v);
        v = fmaf(wv[6], r2[0], v); v = fmaf(wv[7], r2[1], v); v = fmaf(wv[8], r2[2], v);
        float g = 0.5f * v * (1.f + erff(v * 0.70710678118654752440f));
        // conv2's SAME zero-pad: h1 at t=-1 / t=8192 must be exactly 0
        sh1[(s + 1) * SW + c] = ((unsigned)t < T_LEN) ? g : 0.f;
    }
    __syncthreads();

    // ---- phase D: conv2 + GELU + blend + ratio-mean over scales + write ----
    const float blend = 1.f / (1.f + expf(-blendl[0]));
    const float b2v = b2[ch];
    float wl[9];
    #pragma unroll
    for (int i = 0; i < 9; ++i) wl[i] = w2s[i];
    for (int c = 2 + tid; c < TTILE + 2; c += NTH) {
        float acc = 0.f;
        #pragma unroll 4
        for (int s = 1; s <= N_SC; ++s) {
            const float* r0 = sh1 + (s - 1) * SW + (c - 1);
            const float* r1 = r0 + SW;
            const float* r2 = r1 + SW;
            float v = b2v;
            v = fmaf(wl[0], r0[0], v); v = fmaf(wl[1], r0[1], v); v = fmaf(wl[2], r0[2], v);
            v = fmaf(wl[3], r1[0], v); v = fmaf(wl[4], r1[1], v); v = fmaf(wl[5], r1[2], v);
            v = fmaf(wl[6], r2[0], v); v = fmaf(wl[7], r2[1], v); v = fmaf(wl[8], r2[2], v);
            float h  = 0.5f * v * (1.f + erff(v * 0.70710678118654752440f));
            float cw = scw[s * SW + c];
            float bl = blend * h + (1.f - blend) * cw;
            acc += __fdividef(bl, cw + 1e-8f);
        }
        out[(size_t)row * T_LEN + (t0 + c - 2)] = sx[c + 256] * acc * (1.f / 16.f);
    }
}

extern "C" void kernel_launch(void* const* d_in, const int* in_sizes, int n_in,
                              void* d_out, int out_size)
{
    const float* x  = (const float*)d_in[0];
    const float* w1 = (const float*)d_in[1];
    const float* b1 = (const float*)d_in[2];
    const float* w2 = (const float*)d_in[3];
    const float* b2 = (const float*)d_in[4];
    const float* bl = (const float*)d_in[5];
    const float* ls = (const float*)d_in[6];
    float* out = (float*)d_out;

    const int rows = in_sizes[0] / T_LEN;   // B*C = 256

    const size_t smem = (size_t)(SXN + 2 * MAXW + 2 * 18 * SW + 144 + 12) * sizeof(float)
                        + 4 * 16 * sizeof(int);
    cudaFuncSetAttribute(wav_main_kernel, cudaFuncAttributeMaxDynamicSharedMemorySize, (int)smem);

    dim3 igrid(5, N_SC);                   // 5 tap-chunks x 16 scales
    wav_init_kernel<<<igrid, 128>>>();
    dim3 grid(T_LEN / TTILE, rows);
    wav_main_kernel<<<grid, NTH, smem>>>(x, w1, b1, w2, b2, bl, ls, out);
}